// round 14
// baseline (speedup 1.0000x reference)
#include <cuda_runtime.h>
#include <cuda_bf16.h>
#include <cstdint>

// Stage 0 (prep): c2 per centroid + bf16 image of centroids in the exact
//   XOR-swizzled smem byte layout used by ldmatrix (row=n, 512B/row).
// Stage 1 (HMMA, occ-3): 4096 CTAs x 256 thr, A = 64 rows (32KB), B streamed
//   in four 32KB quarters (scores overlay consumed quarter, skew-4 layout).
//   R13 profile: no pipe >28%, occ 23.4% (2-CTA limit), regs=128 (ceiling)
//   -> latency-bound at low occupancy. 64-row tile => 65KB smem => 3 CTAs/SM,
//   reg budget 85 >= ~70 live. Per-dot MMA order unchanged -> scores
//   bit-identical -> same top-8 candidates.
// Stage 2 (exact, validated R12): compensated-fp32 dot2, 8 lanes/row.
// Launch order: prep, dummy, dummy, mma, refine — ncu captures 4th launch.

#define DIM  256
#define KTOT 256
#define NMAX 262144
#define NC   8
#define CROWS 64

__device__ float  g_c2[KTOT];
__device__ int    g_cand[NMAX * NC];
__device__ unsigned long long g_centB[KTOT * DIM * 2 / 8];   // 128KB bf16 B image

__global__ void dummy_kernel() {}

__device__ __forceinline__ uint32_t smem_u32(const void* p) {
    uint32_t a;
    asm("{ .reg .u64 t; cvta.to.shared.u64 t, %1; cvt.u32.u64 %0, t; }" : "=r"(a) : "l"(p));
    return a;
}
__device__ __forceinline__ uint32_t bf16pack(float x, float y) {
    return ((uint32_t)__bfloat16_as_ushort(__float2bfloat16_rn(y)) << 16)
         |  (uint32_t)__bfloat16_as_ushort(__float2bfloat16_rn(x));
}

template <int W>
__device__ __forceinline__ void ins_top(float (&V)[W], int (&I)[W], float v, int k) {
    if (v > V[W - 1] || (v == V[W - 1] && k < I[W - 1])) {
        V[W - 1] = v; I[W - 1] = k;
#pragma unroll
        for (int q = W - 1; q > 0; --q)
            if (V[q] > V[q - 1] || (V[q] == V[q - 1] && I[q] < I[q - 1])) {
                float tv = V[q]; V[q] = V[q - 1]; V[q - 1] = tv;
                int   ti = I[q]; I[q] = I[q - 1]; I[q - 1] = ti;
            }
    }
}

// ---------------- Stage 0: prep (R8 verbatim) ----------------
__global__ void prep_kernel(const float* __restrict__ cent) {
    int k    = (blockIdx.x * blockDim.x + threadIdx.x) >> 5;
    int lane = threadIdx.x & 31;
    const float4* cr = reinterpret_cast<const float4*>(cent + (size_t)k * DIM);
    float4 a = cr[lane], b = cr[lane + 32];
    double s = (double)a.x * a.x + (double)a.y * a.y + (double)a.z * a.z + (double)a.w * a.w
             + (double)b.x * b.x + (double)b.y * b.y + (double)b.z * b.z + (double)b.w * b.w;
#pragma unroll
    for (int o = 16; o; o >>= 1) s += __shfl_xor_sync(0xffffffffu, s, o);
    if (lane == 0) g_c2[k] = (float)s;

#pragma unroll
    for (int h = 0; h < 2; ++h) {
        float4 v = h ? b : a;
        uint32_t d0   = h * 128 + lane * 4;
        uint32_t byte = (uint32_t)k * 512u + ((d0 * 2u) ^ (((uint32_t)k & 7u) << 4));
        g_centB[byte >> 3] = ((unsigned long long)bf16pack(v.z, v.w) << 32)
                           | bf16pack(v.x, v.y);
    }
}

// ---------------- Stage 1: occ-3 HMMA candidate pass ----------------
#define SMEM_A   0                  // 64 x 512B = 32768
#define SMEM_B   32768              // 64 cents x 512B = 32768 (quarter)
#define SMEM_C2  65536              // 1KB
#define SMEM_TOT 66560

#define LDSM_X4(r0, r1, r2, r3, a)                                           \
    asm volatile("ldmatrix.sync.aligned.m8n8.x4.shared.b16 {%0,%1,%2,%3}, [%4];" \
        : "=r"(r0), "=r"(r1), "=r"(r2), "=r"(r3) : "r"(a))

#define MMA16816(c, A, B)                                                    \
    asm volatile("mma.sync.aligned.m16n8k16.row.col.f32.bf16.bf16.f32 "      \
        "{%0,%1,%2,%3}, {%4,%5,%6,%7}, {%8,%9}, {%0,%1,%2,%3};"              \
        : "+f"((c)[0]), "+f"((c)[1]), "+f"((c)[2]), "+f"((c)[3])             \
        : "r"((A)[0]), "r"((A)[1]), "r"((A)[2]), "r"((A)[3]),                \
          "r"((B)[0]), "r"((B)[1]))

__global__ __launch_bounds__(256, 3)
void mma_cand_kernel(const float* __restrict__ emb, int N) {
    extern __shared__ char smem[];
    const uint32_t sb = smem_u32(smem);
    const int tid = threadIdx.x, wid = tid >> 5, l = tid & 31;
    const int wm = wid & 1, wn = wid >> 1;      // 2(M) x 4(N) warps, tile 32x16
    const int n0 = blockIdx.x * CROWS;

    ((float*)(smem + SMEM_C2))[tid] = g_c2[tid];

    // A: fp32 -> bf16, swizzled [row][k] layout (64 rows x 512B)
#pragma unroll 4
    for (int i = 0; i < 16; ++i) {
        int idx = tid + 256 * i, row = idx >> 6, c4 = idx & 63, gr = n0 + row;
        float4 v = make_float4(0.f, 0.f, 0.f, 0.f);
        if (gr < N) v = reinterpret_cast<const float4*>(emb)[(size_t)gr * 64 + c4];
        uint32_t byte = (uint32_t)row * 512u
                      + (((uint32_t)c4 * 8u) ^ (((uint32_t)row & 7u) << 4));
        *reinterpret_cast<uint2*>(smem + SMEM_A + byte) =
            make_uint2(bf16pack(v.x, v.y), bf16pack(v.z, v.w));
    }

    const uint32_t xa  = ((uint32_t)l & 7u) << 4;
    const uint32_t aro = (uint32_t)(wm * 32 + (l & 7) + (l & 8));
    const uint32_t aof0 = sb + SMEM_A + aro * 512u;
    const uint32_t aof1 = aof0 + 16u * 512u;
    const uint32_t ka  = (uint32_t)((l >> 4) & 1) * 16u;
    const uint32_t nb0 = (uint32_t)(wn * 16 + (l & 7) + ((l >> 4) & 1) * 8);
    const uint32_t bof0 = sb + SMEM_B + nb0 * 512u;
    const uint32_t kb  = (uint32_t)((l >> 3) & 1) * 16u;

    // running top-8 per (row, part): 4 parts/row, 64 rows
    const int prow = tid >> 2, ppart = tid & 3;
    float V[NC]; int I[NC];
#pragma unroll
    for (int s = 0; s < NC; ++s) { V[s] = -__int_as_float(0x7f800000); I[s] = s; }

    for (int q = 0; q < 4; ++q) {
        // B quarter copy (pre-swizzled image, contiguous 32KB)
#pragma unroll
        for (int i = 0; i < 8; ++i)
            ((float4*)(smem + SMEM_B))[tid + 256 * i] =
                reinterpret_cast<const float4*>(g_centB)[q * 2048 + tid + 256 * i];
        __syncthreads();             // B(q) + (q==0: A) visible

        float acc[2][2][4];
#pragma unroll
        for (int mt = 0; mt < 2; ++mt)
#pragma unroll
            for (int nt = 0; nt < 2; ++nt)
#pragma unroll
                for (int s = 0; s < 4; ++s) acc[mt][nt][s] = 0.f;

#pragma unroll
        for (int ks = 0; ks < 16; ++ks) {
            const uint32_t kbyte = (uint32_t)ks * 32u;
            uint32_t af[2][4], bfr[2][2];
            LDSM_X4(af[0][0], af[0][1], af[0][2], af[0][3], aof0 + ((kbyte + ka) ^ xa));
            LDSM_X4(af[1][0], af[1][1], af[1][2], af[1][3], aof1 + ((kbyte + ka) ^ xa));
            LDSM_X4(bfr[0][0], bfr[0][1], bfr[1][0], bfr[1][1], bof0 + ((kbyte + kb) ^ xa));
#pragma unroll
            for (int mt = 0; mt < 2; ++mt)
#pragma unroll
                for (int nt = 0; nt < 2; ++nt)
                    MMA16816(acc[mt][nt], af[mt], bfr[nt]);
        }
        __syncthreads();             // B(q) consumed; overlay scores

        // scores s = c2 - 2*dot, skew-4 layout: addr = r*64 + ((c + 4r)&63)
        {
            float* sc = (float*)(smem + SMEM_B);
            const float* c2s = (const float*)(smem + SMEM_C2);
#pragma unroll
            for (int mt = 0; mt < 2; ++mt) {
                int r0 = wm * 32 + mt * 16 + (l >> 2);
                int r1 = r0 + 8;
#pragma unroll
                for (int nt = 0; nt < 2; ++nt) {
                    int c0 = wn * 16 + nt * 8 + 2 * (l & 3);       // local col
                    float c2a = c2s[q * 64 + c0], c2b = c2s[q * 64 + c0 + 1];
                    int a0 = r0 * 64 + ((c0 + 4 * r0) & 63);
                    int a0b = r0 * 64 + ((c0 + 1 + 4 * r0) & 63);
                    int a1 = r1 * 64 + ((c0 + 4 * r1) & 63);
                    int a1b = r1 * 64 + ((c0 + 1 + 4 * r1) & 63);
                    sc[a0]  = c2a - 2.f * acc[mt][nt][0];
                    sc[a0b] = c2b - 2.f * acc[mt][nt][1];
                    sc[a1]  = c2a - 2.f * acc[mt][nt][2];
                    sc[a1b] = c2b - 2.f * acc[mt][nt][3];
                }
            }
        }
        __syncthreads();

        // scan: 4 threads/row, cols c = ppart + 4j (conflict-free under skew-4)
        {
            const float* sc = (const float*)(smem + SMEM_B);
#pragma unroll 4
            for (int j = 0; j < 16; ++j) {
                int c = ppart + 4 * j;
                float v = sc[prow * 64 + ((c + 4 * prow) & 63)];
                ins_top<NC>(V, I, v, q * 64 + c);
            }
        }
        __syncthreads();             // scores consumed before next B copy
    }

    // dump per-part top-8 over A region (A no longer needed)
    {
        float* cv = (float*)smem;                       // 64*4*8*4 = 8KB
        int*   ci = (int*)(smem + 16384);
#pragma unroll
        for (int s = 0; s < NC; ++s) {
            cv[(prow * 4 + ppart) * NC + s] = V[s];
            ci[(prow * 4 + ppart) * NC + s] = I[s];
        }
    }
    __syncthreads();

    if (tid < CROWS) {
        int row = tid, gr = n0 + row;
        if (gr < N) {
            const float* cv = (const float*)smem;
            const int*   ci = (const int*)(smem + 16384);
            float W[NC]; int J[NC];
#pragma unroll
            for (int s = 0; s < NC; ++s) { W[s] = -__int_as_float(0x7f800000); J[s] = s; }
            for (int j = 0; j < 4 * NC; ++j)
                ins_top<NC>(W, J, cv[row * 4 * NC + j], ci[row * 4 * NC + j]);
#pragma unroll
            for (int s = 0; s < NC; ++s) g_cand[(size_t)gr * NC + s] = J[s];
        }
    }
}

// ---------------- Stage 2: compensated-fp32 refine (R12 verbatim) ----------------
__device__ __forceinline__ void two_sum(float a, float b, float& s, float& e) {
    s = a + b;
    float bp = s - a;
    e = (a - (s - bp)) + (b - bp);
}
__device__ __forceinline__ void dot_acc(float a, float b, float& s, float& c) {
    float p = a * b;
    float e = fmaf(a, b, -p);
    float t, e2;
    two_sum(s, p, t, e2);
    s = t;
    c += (e + e2);
}
__device__ __forceinline__ float gred_df(float s, float c) {
#pragma unroll
    for (int o = 4; o; o >>= 1) {
        float so = __shfl_xor_sync(0xffffffffu, s, o);
        float co = __shfl_xor_sync(0xffffffffu, c, o);
        float t, e;
        two_sum(s, so, t, e);
        s = t;
        c += (co + e);
    }
    return s + c;
}

__global__ __launch_bounds__(256)
void refine_kernel(const float* __restrict__ emb,
                   const float* __restrict__ cent,
                   float* __restrict__ out, int N) {
    int warp = (blockIdx.x * blockDim.x + threadIdx.x) >> 5;
    int l    = threadIdx.x & 31;
    int sub  = l >> 3, ll = l & 7;          // 4 rows/warp, 8 lanes/row
    int row  = warp * 4 + sub;
    if (warp * 4 >= N) return;
    if (row >= N) row = N - 1;

    const float4* e4 = reinterpret_cast<const float4*>(emb + (size_t)row * DIM);
    float4 e[8];
#pragma unroll
    for (int i = 0; i < 8; ++i) e[i] = e4[ll + 8 * i];

    float xs = 0.f, xc = 0.f;
#pragma unroll
    for (int i = 0; i < 8; ++i) {
        dot_acc(e[i].x, e[i].x, xs, xc); dot_acc(e[i].y, e[i].y, xs, xc);
        dot_acc(e[i].z, e[i].z, xs, xc); dot_acc(e[i].w, e[i].w, xs, xc);
    }
    float x2f = gred_df(xs, xc);

    float V1 = -__int_as_float(0x7f800000), V2 = V1;
    int   I1 = 0, I2 = 0;

#pragma unroll
    for (int j = 0; j < NC; ++j) {
        int k = g_cand[(size_t)row * NC + j];
        const float4* c4 = reinterpret_cast<const float4*>(cent + (size_t)k * DIM);
        float ds = 0.f, dc = 0.f;
#pragma unroll
        for (int i = 0; i < 8; ++i) {
            float4 b = c4[ll + 8 * i];
            dot_acc(e[i].x, b.x, ds, dc); dot_acc(e[i].y, b.y, ds, dc);
            dot_acc(e[i].z, b.z, ds, dc); dot_acc(e[i].w, b.w, ds, dc);
        }
        float xcf = gred_df(ds, dc);
        float a = __fadd_rn(x2f, g_c2[k]);
        float t = __fadd_rn(a, __fmul_rn(-2.0f, xcf));
        float u = fmaxf(t, 0.0f);
        float r = __fsqrt_rn(u);
        bool b1 = (r > V1) || (r == V1 && k < I1);
        bool b2 = (r > V2) || (r == V2 && k < I2);
        if (b1) { V2 = V1; I2 = I1; V1 = r; I1 = k; }
        else if (b2) { V2 = r; I2 = k; }
    }

    const float4* src = reinterpret_cast<const float4*>(cent + (size_t)I2 * DIM);
    float4*       dst = reinterpret_cast<float4*>(out + (size_t)row * DIM);
#pragma unroll
    for (int i = 0; i < 8; ++i) dst[ll + 8 * i] = src[ll + 8 * i];
}

extern "C" void kernel_launch(void* const* d_in, const int* in_sizes, int n_in,
                              void* d_out, int out_size) {
    const float* emb  = (const float*)d_in[0];
    const float* cent = (const float*)d_in[1];
    float* out = (float*)d_out;
    int N = in_sizes[0] / DIM;

    cudaFuncSetAttribute(mma_cand_kernel,
                         cudaFuncAttributeMaxDynamicSharedMemorySize, SMEM_TOT);

    prep_kernel<<<KTOT / 8, 256>>>(cent);
    dummy_kernel<<<1, 1>>>();
    dummy_kernel<<<1, 1>>>();
    mma_cand_kernel<<<(N + CROWS - 1) / CROWS, 256, SMEM_TOT>>>(emb, N);  // 4th -> ncu
    refine_kernel<<<(N + 31) / 32, 256>>>(emb, cent, out, N);
}

// round 15
// speedup vs baseline: 1.6325x; 1.6325x over previous
#include <cuda_runtime.h>
#include <cuda_bf16.h>
#include <cstdint>

// Stage 0 (prep): c2 per centroid + bf16 image of centroids in the exact
//   XOR-swizzled smem byte layout used by ldmatrix (row=n, 512B/row).
// Stage 1 (HMMA, occ-3): R14 structure (64-row tiles, B in four 32KB
//   quarters) but the top-8 selection is rebuilt: scores packed as
//   positive floats with (255-k) in the low 8 mantissa bits, so selection
//   is a branch-free 16-op fmax/fmin insertion chain (no predicated
//   compare-swap monster, no index regs). R14 profile showed ~9300
//   warp-instr/warp (10x nominal) from ins_top predication = the real sink.
// Stage 2 (exact, validated R12): compensated-fp32 dot2, 8 lanes/row.
// Launch order: prep, dummy, dummy, mma, refine — ncu captures 4th launch.

#define DIM  256
#define KTOT 256
#define NMAX 262144
#define NC   8
#define CROWS 64

__device__ float  g_c2[KTOT];
__device__ int    g_cand[NMAX * NC];
__device__ unsigned long long g_centB[KTOT * DIM * 2 / 8];   // 128KB bf16 B image

__global__ void dummy_kernel() {}

__device__ __forceinline__ uint32_t smem_u32(const void* p) {
    uint32_t a;
    asm("{ .reg .u64 t; cvta.to.shared.u64 t, %1; cvt.u32.u64 %0, t; }" : "=r"(a) : "l"(p));
    return a;
}
__device__ __forceinline__ uint32_t bf16pack(float x, float y) {
    return ((uint32_t)__bfloat16_as_ushort(__float2bfloat16_rn(y)) << 16)
         |  (uint32_t)__bfloat16_as_ushort(__float2bfloat16_rn(x));
}
// branch-free insertion of v into descending sorted V[0..NC-1]
__device__ __forceinline__ void chain_ins(float (&V)[NC], float v) {
#pragma unroll
    for (int s = 0; s < NC; ++s) {
        float hi = fmaxf(V[s], v);
        v = fminf(V[s], v);
        V[s] = hi;
    }
}

// ---------------- Stage 0: prep (R8 verbatim) ----------------
__global__ void prep_kernel(const float* __restrict__ cent) {
    int k    = (blockIdx.x * blockDim.x + threadIdx.x) >> 5;
    int lane = threadIdx.x & 31;
    const float4* cr = reinterpret_cast<const float4*>(cent + (size_t)k * DIM);
    float4 a = cr[lane], b = cr[lane + 32];
    double s = (double)a.x * a.x + (double)a.y * a.y + (double)a.z * a.z + (double)a.w * a.w
             + (double)b.x * b.x + (double)b.y * b.y + (double)b.z * b.z + (double)b.w * b.w;
#pragma unroll
    for (int o = 16; o; o >>= 1) s += __shfl_xor_sync(0xffffffffu, s, o);
    if (lane == 0) g_c2[k] = (float)s;

#pragma unroll
    for (int h = 0; h < 2; ++h) {
        float4 v = h ? b : a;
        uint32_t d0   = h * 128 + lane * 4;
        uint32_t byte = (uint32_t)k * 512u + ((d0 * 2u) ^ (((uint32_t)k & 7u) << 4));
        g_centB[byte >> 3] = ((unsigned long long)bf16pack(v.z, v.w) << 32)
                           | bf16pack(v.x, v.y);
    }
}

// ---------------- Stage 1: occ-3 HMMA candidate pass ----------------
#define SMEM_A   0                  // 64 x 512B = 32768
#define SMEM_B   32768              // 64 cents x 512B = 32768 (quarter)
#define SMEM_C2  65536              // 1KB (c2 + 1024 bias)
#define SMEM_TOT 66560

#define LDSM_X4(r0, r1, r2, r3, a)                                           \
    asm volatile("ldmatrix.sync.aligned.m8n8.x4.shared.b16 {%0,%1,%2,%3}, [%4];" \
        : "=r"(r0), "=r"(r1), "=r"(r2), "=r"(r3) : "r"(a))

#define MMA16816(c, A, B)                                                    \
    asm volatile("mma.sync.aligned.m16n8k16.row.col.f32.bf16.bf16.f32 "      \
        "{%0,%1,%2,%3}, {%4,%5,%6,%7}, {%8,%9}, {%0,%1,%2,%3};"              \
        : "+f"((c)[0]), "+f"((c)[1]), "+f"((c)[2]), "+f"((c)[3])             \
        : "r"((A)[0]), "r"((A)[1]), "r"((A)[2]), "r"((A)[3]),                \
          "r"((B)[0]), "r"((B)[1]))

// pack: positive float (score + 1024) with (255 - k) in low 8 mantissa bits
__device__ __forceinline__ uint32_t pack_score(float s_biased, int k) {
    return (__float_as_uint(s_biased) & 0xFFFFFF00u) | (255u - (uint32_t)k);
}

__global__ __launch_bounds__(256, 3)
void mma_cand_kernel(const float* __restrict__ emb, int N) {
    extern __shared__ char smem[];
    const uint32_t sb = smem_u32(smem);
    const int tid = threadIdx.x, wid = tid >> 5, l = tid & 31;
    const int wm = wid & 1, wn = wid >> 1;      // 2(M) x 4(N) warps, tile 32x16
    const int n0 = blockIdx.x * CROWS;

    ((float*)(smem + SMEM_C2))[tid] = g_c2[tid] + 1024.0f;   // pre-biased

    // A: fp32 -> bf16, swizzled [row][k] layout (64 rows x 512B)
#pragma unroll 4
    for (int i = 0; i < 16; ++i) {
        int idx = tid + 256 * i, row = idx >> 6, c4 = idx & 63, gr = n0 + row;
        float4 v = make_float4(0.f, 0.f, 0.f, 0.f);
        if (gr < N) v = reinterpret_cast<const float4*>(emb)[(size_t)gr * 64 + c4];
        uint32_t byte = (uint32_t)row * 512u
                      + (((uint32_t)c4 * 8u) ^ (((uint32_t)row & 7u) << 4));
        *reinterpret_cast<uint2*>(smem + SMEM_A + byte) =
            make_uint2(bf16pack(v.x, v.y), bf16pack(v.z, v.w));
    }

    const uint32_t xa  = ((uint32_t)l & 7u) << 4;
    const uint32_t aro = (uint32_t)(wm * 32 + (l & 7) + (l & 8));
    const uint32_t aof0 = sb + SMEM_A + aro * 512u;
    const uint32_t aof1 = aof0 + 16u * 512u;
    const uint32_t ka  = (uint32_t)((l >> 4) & 1) * 16u;
    const uint32_t nb0 = (uint32_t)(wn * 16 + (l & 7) + ((l >> 4) & 1) * 8);
    const uint32_t bof0 = sb + SMEM_B + nb0 * 512u;
    const uint32_t kb  = (uint32_t)((l >> 3) & 1) * 16u;

    // running top-8 (packed floats) per (row, part): 4 parts/row, 64 rows
    const int prow = tid >> 2, ppart = tid & 3;
    float V[NC];
#pragma unroll
    for (int s = 0; s < NC; ++s) V[s] = 0.0f;   // below all packed scores

    for (int q = 0; q < 4; ++q) {
        // B quarter copy (pre-swizzled image, contiguous 32KB)
#pragma unroll
        for (int i = 0; i < 8; ++i)
            ((float4*)(smem + SMEM_B))[tid + 256 * i] =
                reinterpret_cast<const float4*>(g_centB)[q * 2048 + tid + 256 * i];
        __syncthreads();             // B(q) + (q==0: A) visible

        float acc[2][2][4];
#pragma unroll
        for (int mt = 0; mt < 2; ++mt)
#pragma unroll
            for (int nt = 0; nt < 2; ++nt)
#pragma unroll
                for (int s = 0; s < 4; ++s) acc[mt][nt][s] = 0.f;

#pragma unroll
        for (int ks = 0; ks < 16; ++ks) {
            const uint32_t kbyte = (uint32_t)ks * 32u;
            uint32_t af[2][4], bfr[2][2];
            LDSM_X4(af[0][0], af[0][1], af[0][2], af[0][3], aof0 + ((kbyte + ka) ^ xa));
            LDSM_X4(af[1][0], af[1][1], af[1][2], af[1][3], aof1 + ((kbyte + ka) ^ xa));
            LDSM_X4(bfr[0][0], bfr[0][1], bfr[1][0], bfr[1][1], bof0 + ((kbyte + kb) ^ xa));
#pragma unroll
            for (int mt = 0; mt < 2; ++mt)
#pragma unroll
                for (int nt = 0; nt < 2; ++nt)
                    MMA16816(acc[mt][nt], af[mt], bfr[nt]);
        }
        __syncthreads();             // B(q) consumed; overlay packed scores

        // packed scores, skew-4 layout: addr = r*64 + ((c + 4r)&63)
        {
            uint32_t* sc = (uint32_t*)(smem + SMEM_B);
            const float* c2s = (const float*)(smem + SMEM_C2);
#pragma unroll
            for (int mt = 0; mt < 2; ++mt) {
                int r0 = wm * 32 + mt * 16 + (l >> 2);
                int r1 = r0 + 8;
#pragma unroll
                for (int nt = 0; nt < 2; ++nt) {
                    int c0 = wn * 16 + nt * 8 + 2 * (l & 3);       // local col
                    int kg = q * 64 + c0;                          // global col
                    float c2a = c2s[kg], c2b = c2s[kg + 1];
                    int a0  = r0 * 64 + ((c0 + 4 * r0) & 63);
                    int a0b = r0 * 64 + ((c0 + 1 + 4 * r0) & 63);
                    int a1  = r1 * 64 + ((c0 + 4 * r1) & 63);
                    int a1b = r1 * 64 + ((c0 + 1 + 4 * r1) & 63);
                    sc[a0]  = pack_score(c2a - 2.f * acc[mt][nt][0], kg);
                    sc[a0b] = pack_score(c2b - 2.f * acc[mt][nt][1], kg + 1);
                    sc[a1]  = pack_score(c2a - 2.f * acc[mt][nt][2], kg);
                    sc[a1b] = pack_score(c2b - 2.f * acc[mt][nt][3], kg + 1);
                }
            }
        }
        __syncthreads();

        // scan: 4 threads/row, cols c = ppart + 4j; branch-free chains
        {
            const uint32_t* sc = (const uint32_t*)(smem + SMEM_B);
#pragma unroll 4
            for (int j = 0; j < 16; ++j) {
                int c = ppart + 4 * j;
                chain_ins(V, __uint_as_float(sc[prow * 64 + ((c + 4 * prow) & 63)]));
            }
        }
        __syncthreads();             // scores consumed before next B copy
    }

    // dump per-part top-8 over A region (A no longer needed): 64*4*8*4 = 8KB
    {
        float* cv = (float*)smem;
#pragma unroll
        for (int s = 0; s < NC; ++s)
            cv[(prow * 4 + ppart) * NC + s] = V[s];
    }
    __syncthreads();

    if (tid < CROWS) {
        int row = tid, gr = n0 + row;
        if (gr < N) {
            const float* cv = (const float*)smem;
            float W[NC];
#pragma unroll
            for (int s = 0; s < NC; ++s) W[s] = 0.0f;
            for (int j = 0; j < 4 * NC; ++j)
                chain_ins(W, cv[row * 4 * NC + j]);
#pragma unroll
            for (int s = 0; s < NC; ++s)
                g_cand[(size_t)gr * NC + s] = 255 - (int)(__float_as_uint(W[s]) & 0xFFu);
        }
    }
}

// ---------------- Stage 2: compensated-fp32 refine (R12 verbatim) ----------------
__device__ __forceinline__ void two_sum(float a, float b, float& s, float& e) {
    s = a + b;
    float bp = s - a;
    e = (a - (s - bp)) + (b - bp);
}
__device__ __forceinline__ void dot_acc(float a, float b, float& s, float& c) {
    float p = a * b;
    float e = fmaf(a, b, -p);
    float t, e2;
    two_sum(s, p, t, e2);
    s = t;
    c += (e + e2);
}
__device__ __forceinline__ float gred_df(float s, float c) {
#pragma unroll
    for (int o = 4; o; o >>= 1) {
        float so = __shfl_xor_sync(0xffffffffu, s, o);
        float co = __shfl_xor_sync(0xffffffffu, c, o);
        float t, e;
        two_sum(s, so, t, e);
        s = t;
        c += (co + e);
    }
    return s + c;
}

__global__ __launch_bounds__(256)
void refine_kernel(const float* __restrict__ emb,
                   const float* __restrict__ cent,
                   float* __restrict__ out, int N) {
    int warp = (blockIdx.x * blockDim.x + threadIdx.x) >> 5;
    int l    = threadIdx.x & 31;
    int sub  = l >> 3, ll = l & 7;          // 4 rows/warp, 8 lanes/row
    int row  = warp * 4 + sub;
    if (warp * 4 >= N) return;
    if (row >= N) row = N - 1;

    const float4* e4 = reinterpret_cast<const float4*>(emb + (size_t)row * DIM);
    float4 e[8];
#pragma unroll
    for (int i = 0; i < 8; ++i) e[i] = e4[ll + 8 * i];

    float xs = 0.f, xc = 0.f;
#pragma unroll
    for (int i = 0; i < 8; ++i) {
        dot_acc(e[i].x, e[i].x, xs, xc); dot_acc(e[i].y, e[i].y, xs, xc);
        dot_acc(e[i].z, e[i].z, xs, xc); dot_acc(e[i].w, e[i].w, xs, xc);
    }
    float x2f = gred_df(xs, xc);

    float V1 = -__int_as_float(0x7f800000), V2 = V1;
    int   I1 = 0, I2 = 0;

#pragma unroll
    for (int j = 0; j < NC; ++j) {
        int k = g_cand[(size_t)row * NC + j];
        const float4* c4 = reinterpret_cast<const float4*>(cent + (size_t)k * DIM);
        float ds = 0.f, dc = 0.f;
#pragma unroll
        for (int i = 0; i < 8; ++i) {
            float4 b = c4[ll + 8 * i];
            dot_acc(e[i].x, b.x, ds, dc); dot_acc(e[i].y, b.y, ds, dc);
            dot_acc(e[i].z, b.z, ds, dc); dot_acc(e[i].w, b.w, ds, dc);
        }
        float xcf = gred_df(ds, dc);
        float a = __fadd_rn(x2f, g_c2[k]);
        float t = __fadd_rn(a, __fmul_rn(-2.0f, xcf));
        float u = fmaxf(t, 0.0f);
        float r = __fsqrt_rn(u);
        bool b1 = (r > V1) || (r == V1 && k < I1);
        bool b2 = (r > V2) || (r == V2 && k < I2);
        if (b1) { V2 = V1; I2 = I1; V1 = r; I1 = k; }
        else if (b2) { V2 = r; I2 = k; }
    }

    const float4* src = reinterpret_cast<const float4*>(cent + (size_t)I2 * DIM);
    float4*       dst = reinterpret_cast<float4*>(out + (size_t)row * DIM);
#pragma unroll
    for (int i = 0; i < 8; ++i) dst[ll + 8 * i] = src[ll + 8 * i];
}

extern "C" void kernel_launch(void* const* d_in, const int* in_sizes, int n_in,
                              void* d_out, int out_size) {
    const float* emb  = (const float*)d_in[0];
    const float* cent = (const float*)d_in[1];
    float* out = (float*)d_out;
    int N = in_sizes[0] / DIM;

    cudaFuncSetAttribute(mma_cand_kernel,
                         cudaFuncAttributeMaxDynamicSharedMemorySize, SMEM_TOT);

    prep_kernel<<<KTOT / 8, 256>>>(cent);
    dummy_kernel<<<1, 1>>>();
    dummy_kernel<<<1, 1>>>();
    mma_cand_kernel<<<(N + CROWS - 1) / CROWS, 256, SMEM_TOT>>>(emb, N);  // 4th -> ncu
    refine_kernel<<<(N + 31) / 32, 256>>>(emb, cent, out, N);
}

// round 16
// speedup vs baseline: 1.6661x; 1.0205x over previous
#include <cuda_runtime.h>
#include <cuda_bf16.h>
#include <cstdint>

// Stage 0 (prep): c2 per centroid + bf16 image of centroids in the exact
//   XOR-swizzled smem byte layout used by ldmatrix (row=n, 512B/row).
// Stage 1 (HMMA, occ-2, 32x32 warp tiles): 4096 CTAs x 256 thr, A = 64 rows
//   (32KB), B streamed in two 64KB halves (128 cols). Warp grid 2(M)x4(N),
//   tile 32x32 -> LDSM:MMA = 0.5 (was 0.75) — R15 profile showed L1=75.4%
//   (LDSM-bound mainloop). Selection: packed-score fmax/fmin chains (R15).
//   Per-dot MMA order unchanged -> scores bit-identical -> same candidates.
// Stage 2 (exact, validated R12): compensated-fp32 dot2, 8 lanes/row.
// Launch order: prep, dummy, dummy, mma, refine — ncu captures 4th launch.

#define DIM  256
#define KTOT 256
#define NMAX 262144
#define NC   8
#define CROWS 64

__device__ float  g_c2[KTOT];
__device__ int    g_cand[NMAX * NC];
__device__ unsigned long long g_centB[KTOT * DIM * 2 / 8];   // 128KB bf16 B image

__global__ void dummy_kernel() {}

__device__ __forceinline__ uint32_t smem_u32(const void* p) {
    uint32_t a;
    asm("{ .reg .u64 t; cvta.to.shared.u64 t, %1; cvt.u32.u64 %0, t; }" : "=r"(a) : "l"(p));
    return a;
}
__device__ __forceinline__ uint32_t bf16pack(float x, float y) {
    return ((uint32_t)__bfloat16_as_ushort(__float2bfloat16_rn(y)) << 16)
         |  (uint32_t)__bfloat16_as_ushort(__float2bfloat16_rn(x));
}
// branch-free insertion of v into descending sorted V[0..NC-1]
__device__ __forceinline__ void chain_ins(float (&V)[NC], float v) {
#pragma unroll
    for (int s = 0; s < NC; ++s) {
        float hi = fmaxf(V[s], v);
        v = fminf(V[s], v);
        V[s] = hi;
    }
}

// ---------------- Stage 0: prep (R8 verbatim) ----------------
__global__ void prep_kernel(const float* __restrict__ cent) {
    int k    = (blockIdx.x * blockDim.x + threadIdx.x) >> 5;
    int lane = threadIdx.x & 31;
    const float4* cr = reinterpret_cast<const float4*>(cent + (size_t)k * DIM);
    float4 a = cr[lane], b = cr[lane + 32];
    double s = (double)a.x * a.x + (double)a.y * a.y + (double)a.z * a.z + (double)a.w * a.w
             + (double)b.x * b.x + (double)b.y * b.y + (double)b.z * b.z + (double)b.w * b.w;
#pragma unroll
    for (int o = 16; o; o >>= 1) s += __shfl_xor_sync(0xffffffffu, s, o);
    if (lane == 0) g_c2[k] = (float)s;

#pragma unroll
    for (int h = 0; h < 2; ++h) {
        float4 v = h ? b : a;
        uint32_t d0   = h * 128 + lane * 4;
        uint32_t byte = (uint32_t)k * 512u + ((d0 * 2u) ^ (((uint32_t)k & 7u) << 4));
        g_centB[byte >> 3] = ((unsigned long long)bf16pack(v.z, v.w) << 32)
                           | bf16pack(v.x, v.y);
    }
}

// ---------------- Stage 1: occ-2 HMMA candidate pass, 32x32 warp tiles ----------------
#define SMEM_A   0                  // 64 x 512B = 32768
#define SMEM_B   32768              // 128 cents x 512B = 65536 (half)
#define SMEM_C2  98304              // 1KB (c2 + 1024 bias)
#define SMEM_TOT 99328

#define LDSM_X4(r0, r1, r2, r3, a)                                           \
    asm volatile("ldmatrix.sync.aligned.m8n8.x4.shared.b16 {%0,%1,%2,%3}, [%4];" \
        : "=r"(r0), "=r"(r1), "=r"(r2), "=r"(r3) : "r"(a))

#define MMA16816(c, A, B)                                                    \
    asm volatile("mma.sync.aligned.m16n8k16.row.col.f32.bf16.bf16.f32 "      \
        "{%0,%1,%2,%3}, {%4,%5,%6,%7}, {%8,%9}, {%0,%1,%2,%3};"              \
        : "+f"((c)[0]), "+f"((c)[1]), "+f"((c)[2]), "+f"((c)[3])             \
        : "r"((A)[0]), "r"((A)[1]), "r"((A)[2]), "r"((A)[3]),                \
          "r"((B)[0]), "r"((B)[1]))

// pack: positive float (score + 1024) with (255 - k) in low 8 mantissa bits
__device__ __forceinline__ uint32_t pack_score(float s_biased, int k) {
    return (__float_as_uint(s_biased) & 0xFFFFFF00u) | (255u - (uint32_t)k);
}

__global__ __launch_bounds__(256, 2)
void mma_cand_kernel(const float* __restrict__ emb, int N) {
    extern __shared__ char smem[];
    const uint32_t sb = smem_u32(smem);
    const int tid = threadIdx.x, wid = tid >> 5, l = tid & 31;
    const int wm = wid & 1, wn = wid >> 1;      // 2(M) x 4(N) warps, tile 32x32
    const int n0 = blockIdx.x * CROWS;

    ((float*)(smem + SMEM_C2))[tid] = g_c2[tid] + 1024.0f;   // pre-biased

    // A: fp32 -> bf16, swizzled [row][k] layout (64 rows x 512B)
#pragma unroll 4
    for (int i = 0; i < 16; ++i) {
        int idx = tid + 256 * i, row = idx >> 6, c4 = idx & 63, gr = n0 + row;
        float4 v = make_float4(0.f, 0.f, 0.f, 0.f);
        if (gr < N) v = reinterpret_cast<const float4*>(emb)[(size_t)gr * 64 + c4];
        uint32_t byte = (uint32_t)row * 512u
                      + (((uint32_t)c4 * 8u) ^ (((uint32_t)row & 7u) << 4));
        *reinterpret_cast<uint2*>(smem + SMEM_A + byte) =
            make_uint2(bf16pack(v.x, v.y), bf16pack(v.z, v.w));
    }

    const uint32_t xa  = ((uint32_t)l & 7u) << 4;
    const uint32_t aro = (uint32_t)(wm * 32 + (l & 7) + (l & 8));
    const uint32_t aof0 = sb + SMEM_A + aro * 512u;
    const uint32_t aof1 = aof0 + 16u * 512u;
    const uint32_t ka  = (uint32_t)((l >> 4) & 1) * 16u;
    const uint32_t nb0 = (uint32_t)(wn * 32 + (l & 7) + ((l >> 4) & 1) * 8);
    const uint32_t bof0 = sb + SMEM_B + nb0 * 512u;
    const uint32_t bof1 = bof0 + 16u * 512u;
    const uint32_t kb  = (uint32_t)((l >> 3) & 1) * 16u;

    // running top-8 (packed floats) per (row, part): 4 parts/row, 64 rows
    const int prow = tid >> 2, ppart = tid & 3;
    float V[NC];
#pragma unroll
    for (int s = 0; s < NC; ++s) V[s] = 0.0f;   // below all packed scores

    for (int q = 0; q < 2; ++q) {
        // B half copy (pre-swizzled image, contiguous 64KB)
#pragma unroll
        for (int i = 0; i < 16; ++i)
            ((float4*)(smem + SMEM_B))[tid + 256 * i] =
                reinterpret_cast<const float4*>(g_centB)[q * 4096 + tid + 256 * i];
        __syncthreads();             // B(q) + (q==0: A) visible

        float acc[2][4][4];
#pragma unroll
        for (int mt = 0; mt < 2; ++mt)
#pragma unroll
            for (int nt = 0; nt < 4; ++nt)
#pragma unroll
                for (int s = 0; s < 4; ++s) acc[mt][nt][s] = 0.f;

#pragma unroll
        for (int ks = 0; ks < 16; ++ks) {
            const uint32_t kbyte = (uint32_t)ks * 32u;
            uint32_t af[2][4], bfr[4][2];
            LDSM_X4(af[0][0], af[0][1], af[0][2], af[0][3], aof0 + ((kbyte + ka) ^ xa));
            LDSM_X4(af[1][0], af[1][1], af[1][2], af[1][3], aof1 + ((kbyte + ka) ^ xa));
            LDSM_X4(bfr[0][0], bfr[0][1], bfr[1][0], bfr[1][1], bof0 + ((kbyte + kb) ^ xa));
            LDSM_X4(bfr[2][0], bfr[2][1], bfr[3][0], bfr[3][1], bof1 + ((kbyte + kb) ^ xa));
#pragma unroll
            for (int mt = 0; mt < 2; ++mt)
#pragma unroll
                for (int nt = 0; nt < 4; ++nt)
                    MMA16816(acc[mt][nt], af[mt], bfr[nt]);
        }
        __syncthreads();             // B(q) consumed; overlay packed scores

        // packed scores, skew-4 layout: addr = r*128 + ((c + 4r)&127)
        {
            uint32_t* sc = (uint32_t*)(smem + SMEM_B);
            const float* c2s = (const float*)(smem + SMEM_C2);
#pragma unroll
            for (int mt = 0; mt < 2; ++mt) {
                int r0 = wm * 32 + mt * 16 + (l >> 2);
                int r1 = r0 + 8;
#pragma unroll
                for (int nt = 0; nt < 4; ++nt) {
                    int c0 = wn * 32 + nt * 8 + 2 * (l & 3);       // local col
                    int kg = q * 128 + c0;                         // global col
                    float c2a = c2s[kg], c2b = c2s[kg + 1];
                    int a0  = r0 * 128 + ((c0 + 4 * r0) & 127);
                    int a0b = r0 * 128 + ((c0 + 1 + 4 * r0) & 127);
                    int a1  = r1 * 128 + ((c0 + 4 * r1) & 127);
                    int a1b = r1 * 128 + ((c0 + 1 + 4 * r1) & 127);
                    sc[a0]  = pack_score(c2a - 2.f * acc[mt][nt][0], kg);
                    sc[a0b] = pack_score(c2b - 2.f * acc[mt][nt][1], kg + 1);
                    sc[a1]  = pack_score(c2a - 2.f * acc[mt][nt][2], kg);
                    sc[a1b] = pack_score(c2b - 2.f * acc[mt][nt][3], kg + 1);
                }
            }
        }
        __syncthreads();

        // scan: 4 threads/row, cols c = ppart + 4j (conflict-free under skew-4)
        {
            const uint32_t* sc = (const uint32_t*)(smem + SMEM_B);
#pragma unroll 4
            for (int j = 0; j < 32; ++j) {
                int c = ppart + 4 * j;
                chain_ins(V, __uint_as_float(sc[prow * 128 + ((c + 4 * prow) & 127)]));
            }
        }
        __syncthreads();             // scores consumed before next B copy
    }

    // dump per-part top-8 over A region (A no longer needed): 64*4*8*4 = 8KB
    {
        float* cv = (float*)smem;
#pragma unroll
        for (int s = 0; s < NC; ++s)
            cv[(prow * 4 + ppart) * NC + s] = V[s];
    }
    __syncthreads();

    if (tid < CROWS) {
        int row = tid, gr = n0 + row;
        if (gr < N) {
            const float* cv = (const float*)smem;
            float W[NC];
#pragma unroll
            for (int s = 0; s < NC; ++s) W[s] = 0.0f;
            for (int j = 0; j < 4 * NC; ++j)
                chain_ins(W, cv[row * 4 * NC + j]);
#pragma unroll
            for (int s = 0; s < NC; ++s)
                g_cand[(size_t)gr * NC + s] = 255 - (int)(__float_as_uint(W[s]) & 0xFFu);
        }
    }
}

// ---------------- Stage 2: compensated-fp32 refine (R12 verbatim) ----------------
__device__ __forceinline__ void two_sum(float a, float b, float& s, float& e) {
    s = a + b;
    float bp = s - a;
    e = (a - (s - bp)) + (b - bp);
}
__device__ __forceinline__ void dot_acc(float a, float b, float& s, float& c) {
    float p = a * b;
    float e = fmaf(a, b, -p);
    float t, e2;
    two_sum(s, p, t, e2);
    s = t;
    c += (e + e2);
}
__device__ __forceinline__ float gred_df(float s, float c) {
#pragma unroll
    for (int o = 4; o; o >>= 1) {
        float so = __shfl_xor_sync(0xffffffffu, s, o);
        float co = __shfl_xor_sync(0xffffffffu, c, o);
        float t, e;
        two_sum(s, so, t, e);
        s = t;
        c += (co + e);
    }
    return s + c;
}

__global__ __launch_bounds__(256)
void refine_kernel(const float* __restrict__ emb,
                   const float* __restrict__ cent,
                   float* __restrict__ out, int N) {
    int warp = (blockIdx.x * blockDim.x + threadIdx.x) >> 5;
    int l    = threadIdx.x & 31;
    int sub  = l >> 3, ll = l & 7;          // 4 rows/warp, 8 lanes/row
    int row  = warp * 4 + sub;
    if (warp * 4 >= N) return;
    if (row >= N) row = N - 1;

    const float4* e4 = reinterpret_cast<const float4*>(emb + (size_t)row * DIM);
    float4 e[8];
#pragma unroll
    for (int i = 0; i < 8; ++i) e[i] = e4[ll + 8 * i];

    float xs = 0.f, xc = 0.f;
#pragma unroll
    for (int i = 0; i < 8; ++i) {
        dot_acc(e[i].x, e[i].x, xs, xc); dot_acc(e[i].y, e[i].y, xs, xc);
        dot_acc(e[i].z, e[i].z, xs, xc); dot_acc(e[i].w, e[i].w, xs, xc);
    }
    float x2f = gred_df(xs, xc);

    float V1 = -__int_as_float(0x7f800000), V2 = V1;
    int   I1 = 0, I2 = 0;

#pragma unroll
    for (int j = 0; j < NC; ++j) {
        int k = g_cand[(size_t)row * NC + j];
        const float4* c4 = reinterpret_cast<const float4*>(cent + (size_t)k * DIM);
        float ds = 0.f, dc = 0.f;
#pragma unroll
        for (int i = 0; i < 8; ++i) {
            float4 b = c4[ll + 8 * i];
            dot_acc(e[i].x, b.x, ds, dc); dot_acc(e[i].y, b.y, ds, dc);
            dot_acc(e[i].z, b.z, ds, dc); dot_acc(e[i].w, b.w, ds, dc);
        }
        float xcf = gred_df(ds, dc);
        float a = __fadd_rn(x2f, g_c2[k]);
        float t = __fadd_rn(a, __fmul_rn(-2.0f, xcf));
        float u = fmaxf(t, 0.0f);
        float r = __fsqrt_rn(u);
        bool b1 = (r > V1) || (r == V1 && k < I1);
        bool b2 = (r > V2) || (r == V2 && k < I2);
        if (b1) { V2 = V1; I2 = I1; V1 = r; I1 = k; }
        else if (b2) { V2 = r; I2 = k; }
    }

    const float4* src = reinterpret_cast<const float4*>(cent + (size_t)I2 * DIM);
    float4*       dst = reinterpret_cast<float4*>(out + (size_t)row * DIM);
#pragma unroll
    for (int i = 0; i < 8; ++i) dst[ll + 8 * i] = src[ll + 8 * i];
}

extern "C" void kernel_launch(void* const* d_in, const int* in_sizes, int n_in,
                              void* d_out, int out_size) {
    const float* emb  = (const float*)d_in[0];
    const float* cent = (const float*)d_in[1];
    float* out = (float*)d_out;
    int N = in_sizes[0] / DIM;

    cudaFuncSetAttribute(mma_cand_kernel,
                         cudaFuncAttributeMaxDynamicSharedMemorySize, SMEM_TOT);

    prep_kernel<<<KTOT / 8, 256>>>(cent);
    dummy_kernel<<<1, 1>>>();
    dummy_kernel<<<1, 1>>>();
    mma_cand_kernel<<<(N + CROWS - 1) / CROWS, 256, SMEM_TOT>>>(emb, N);  // 4th -> ncu
    refine_kernel<<<(N + 31) / 32, 256>>>(emb, cent, out, N);
}